// round 2
// baseline (speedup 1.0000x reference)
#include <cuda_runtime.h>
#include <cstdint>

// Problem constants (match reference)
#define NN      100000
#define EE      3200000
#define GAMMA   0.1f
#define EPSN    1e-12f

// out[i] = -gamma * v[i]   (initialize accumulator with damping term)
__global__ void init_damping_kernel(const float* __restrict__ v,
                                    float* __restrict__ out, int n) {
    int i = blockIdx.x * blockDim.x + threadIdx.x;
    if (i < n) {
        float2 vv = reinterpret_cast<const float2*>(v)[i];
        float2 o;
        o.x = -GAMMA * vv.x;
        o.y = -GAMMA * vv.y;
        reinterpret_cast<float2*>(out)[i] = o;
    }
}

__device__ __forceinline__ void red_add_v2(float* addr, float a, float b) {
    asm volatile("red.global.add.v2.f32 [%0], {%1, %2};"
                 :: "l"(addr), "f"(a), "f"(b) : "memory");
}

__device__ __forceinline__ int4 ldcs_int4(const int4* p) {
    int4 r;
    asm volatile("ld.global.cs.v4.s32 {%0,%1,%2,%3}, [%4];"
                 : "=r"(r.x), "=r"(r.y), "=r"(r.z), "=r"(r.w) : "l"(p));
    return r;
}

// Each thread handles 8 edges: 2x int4 index loads per array,
// 16 position gathers batched for MLP, then 8 vector REDs.
__global__ void __launch_bounds__(256) edge_force_kernel(
        const float* __restrict__ x,
        const int*   __restrict__ src,
        const int*   __restrict__ dst,
        float* __restrict__ out) {
    int t = blockIdx.x * blockDim.x + threadIdx.x;
    int e8 = t * 8;
    if (e8 >= EE) return;

    const float2* __restrict__ x2 = reinterpret_cast<const float2*>(x);

    int4 s4a = ldcs_int4(reinterpret_cast<const int4*>(src) + 2 * t);
    int4 s4b = ldcs_int4(reinterpret_cast<const int4*>(src) + 2 * t + 1);
    int4 d4a = ldcs_int4(reinterpret_cast<const int4*>(dst) + 2 * t);
    int4 d4b = ldcs_int4(reinterpret_cast<const int4*>(dst) + 2 * t + 1);

    int ss[8] = {s4a.x, s4a.y, s4a.z, s4a.w, s4b.x, s4b.y, s4b.z, s4b.w};
    int dd[8] = {d4a.x, d4a.y, d4a.z, d4a.w, d4b.x, d4b.y, d4b.z, d4b.w};

    // Batch all 16 gathers first to maximize outstanding loads.
    float2 xs[8], xd[8];
#pragma unroll
    for (int k = 0; k < 8; k++) {
        xs[k] = __ldg(&x2[ss[k]]);
        xd[k] = __ldg(&x2[dd[k]]);
    }

#pragma unroll
    for (int k = 0; k < 8; k++) {
        float drx = xd[k].x - xs[k].x;
        float dry = xd[k].y - xs[k].y;
        float ab  = sqrtf(drx * drx + dry * dry);
        // force magnitude = -C*P*(ab - R_C)^(P-1) = -2*(ab - 1)
        // message = force * unit_dr = -2*(ab-1)/max(ab,eps) * dr
        float inv = 1.0f / fmaxf(ab, EPSN);
        float f   = -2.0f * (ab - 1.0f) * inv;
        red_add_v2(out + 2 * dd[k], f * drx, f * dry);
    }
}

extern "C" void kernel_launch(void* const* d_in, const int* in_sizes, int n_in,
                              void* d_out, int out_size) {
    const float* x   = (const float*)d_in[0];
    const float* v   = (const float*)d_in[1];
    const int*   src = (const int*)d_in[2];
    const int*   dst = (const int*)d_in[3];
    float* out = (float*)d_out;

    // Init: out = -gamma * v  (N float2 elements)
    {
        int n = NN;
        int threads = 256;
        int blocks = (n + threads - 1) / threads;
        init_damping_kernel<<<blocks, threads>>>(v, out, n);
    }
    // Edge scatter: 8 edges per thread
    {
        int nthreads_total = EE / 8;          // 400000
        int threads = 256;
        int blocks = (nthreads_total + threads - 1) / threads;  // 1563
        edge_force_kernel<<<blocks, threads>>>(x, src, dst, out);
    }
}

// round 3
// speedup vs baseline: 1.0544x; 1.0544x over previous
#include <cuda_runtime.h>
#include <cstdint>

// Problem constants (match reference)
#define NN      100000
#define EE      3200000
#define GAMMA   0.1f

__device__ __forceinline__ void red_add_v2(float* addr, float a, float b) {
    asm volatile("red.global.add.v2.f32 [%0], {%1, %2};"
                 :: "l"(addr), "f"(a), "f"(b) : "memory");
}

__device__ __forceinline__ int4 ldcs_int4(const int4* p) {
    int4 r;
    asm volatile("ld.global.cs.v4.s32 {%0,%1,%2,%3}, [%4];"
                 : "=r"(r.x), "=r"(r.y), "=r"(r.z), "=r"(r.w) : "l"(p));
    return r;
}

#define EDGE_THREADS (EE / 4)          // 800000
#define TOTAL_THREADS (EDGE_THREADS + NN)  // 900000

// Single fused kernel over zero-initialized out:
//   threads [0, EE/4):       4 edges each -> red.add message into out[dst]
//   threads [EE/4, +NN):     damping   -> red.add(-gamma*v[i]) into out[i]
// All contributions are atomic adds, so no ordering is required.
__global__ void __launch_bounds__(256) fused_edge_damp_kernel(
        const float* __restrict__ x,
        const float* __restrict__ v,
        const int*   __restrict__ src,
        const int*   __restrict__ dst,
        float* __restrict__ out) {
    int t = blockIdx.x * blockDim.x + threadIdx.x;

    if (t < EDGE_THREADS) {
        const float2* __restrict__ x2 = reinterpret_cast<const float2*>(x);

        int4 s4 = ldcs_int4(reinterpret_cast<const int4*>(src) + t);
        int4 d4 = ldcs_int4(reinterpret_cast<const int4*>(dst) + t);

        int ss[4] = {s4.x, s4.y, s4.z, s4.w};
        int dd[4] = {d4.x, d4.y, d4.z, d4.w};

        float2 xs[4], xd[4];
#pragma unroll
        for (int k = 0; k < 4; k++) {
            xs[k] = __ldg(&x2[ss[k]]);
            xd[k] = __ldg(&x2[dd[k]]);
        }

#pragma unroll
        for (int k = 0; k < 4; k++) {
            float drx = xd[k].x - xs[k].x;
            float dry = xd[k].y - xs[k].y;
            float d2  = fmaf(drx, drx, dry * dry);
            // f = -C*P*(ab - R_C)/ab = -2 + 2/ab = 2*rsqrt(d2) - 2
            // d2 == 0 (src==dst): reference message is exactly 0.
            float f = (d2 > 0.0f) ? fmaf(2.0f, rsqrtf(d2), -2.0f) : 0.0f;
            red_add_v2(out + 2 * dd[k], f * drx, f * dry);
        }
    } else {
        int i = t - EDGE_THREADS;
        if (i < NN) {
            float2 vv = __ldg(&reinterpret_cast<const float2*>(v)[i]);
            red_add_v2(out + 2 * i, -GAMMA * vv.x, -GAMMA * vv.y);
        }
    }
}

extern "C" void kernel_launch(void* const* d_in, const int* in_sizes, int n_in,
                              void* d_out, int out_size) {
    const float* x   = (const float*)d_in[0];
    const float* v   = (const float*)d_in[1];
    const int*   src = (const int*)d_in[2];
    const int*   dst = (const int*)d_in[3];
    float* out = (float*)d_out;

    // Zero the accumulator (graph-capturable memset node).
    cudaMemsetAsync(out, 0, (size_t)out_size * sizeof(float), 0);

    int threads = 256;
    int blocks = (TOTAL_THREADS + threads - 1) / threads;  // 3516
    fused_edge_damp_kernel<<<blocks, threads>>>(x, v, src, dst, out);
}